// round 1
// baseline (speedup 1.0000x reference)
#include <cuda_runtime.h>
#include <cstdint>
#include <cstddef>

#define T_   2048
#define D_   256
#define NN_  2048
#define NH_  4
#define NL_  6
#define VOCAB_ 256
#define EPS_ 1e-5f
#define TWO_PI_ 6.283185307179586f
#define INV_2PI_ 0.15915494309189535f

// ---------------- scratch (device globals; no allocations) ----------------
__device__ float g_x   [(size_t)T_ * D_];          //  2 MB  current hidden (T,D)
__device__ float g_pc  [(size_t)T_ * NN_];         // 16 MB  rope cos table
__device__ float g_ps  [(size_t)T_ * NN_];         // 16 MB  rope sin table
__device__ float g_xs  [(size_t)NH_ * T_ * NN_];   // 64 MB  x_sparse
__device__ float g_qr  [(size_t)NH_ * T_ * NN_];   // 64 MB  rope(x_sparse), later xy
__device__ float g_sc  [(size_t)NH_ * T_ * T_];    // 64 MB  scores (lower triangle valid)
__device__ float g_ykv [(size_t)NH_ * T_ * D_];    //  8 MB  yKV
__device__ float g_part[(size_t)8  * T_ * D_];     // 16 MB  split-K partials for decoder GEMM

// ---------------- block reduction over 256 threads ----------------
__device__ __forceinline__ float blk_sum256(float v) {
    __shared__ float sb[8];
    #pragma unroll
    for (int o = 16; o; o >>= 1) v += __shfl_xor_sync(0xffffffffu, v, o);
    int tid = threadIdx.x;
    if ((tid & 31) == 0) sb[tid >> 5] = v;
    __syncthreads();
    if (tid == 0) {
        float s = 0.f;
        #pragma unroll
        for (int i = 0; i < 8; i++) s += sb[i];
        sb[0] = s;
    }
    __syncthreads();
    float r = sb[0];
    __syncthreads();   // protect sb before next call
    return r;
}

// ---------------- GEMM tile loaders (128x128x16, 256 threads) ----------------
// A tile: 128 rows x 16 k, source row-major with leading dim ld. Stored transposed As[k][m].
__device__ __forceinline__ void load_tileT(float (&dst)[16][128], const float* __restrict__ src,
                                           int ld, int kbase) {
    int tid = threadIdx.x;
    #pragma unroll
    for (int it = 0; it < 2; ++it) {
        int q = tid + it * 256;
        int r = q >> 2;
        int c = (q & 3) * 4;
        float4 v = *reinterpret_cast<const float4*>(src + (size_t)r * ld + kbase + c);
        dst[c + 0][r] = v.x; dst[c + 1][r] = v.y; dst[c + 2][r] = v.z; dst[c + 3][r] = v.w;
    }
}
// B tile: 16 k x 128 n, source row-major K x N (src already offset to n0). Direct Bs[k][n].
__device__ __forceinline__ void load_tileB(float (&dst)[16][128], const float* __restrict__ src,
                                           int ld, int kbase) {
    int tid = threadIdx.x;
    #pragma unroll
    for (int it = 0; it < 2; ++it) {
        int q = tid + it * 256;
        int r = q >> 5;
        int c = (q & 31) * 4;
        float4 v = *reinterpret_cast<const float4*>(src + (size_t)(kbase + r) * ld + c);
        *reinterpret_cast<float4*>(&dst[r][c]) = v;
    }
}

__device__ __forceinline__ void gemm_compute(const float (&As)[16][128], const float (&Bs)[16][128],
                                             float (&acc)[8][8], int tx, int ty) {
    #pragma unroll
    for (int k = 0; k < 16; k++) {
        float a[8], b[8];
        *reinterpret_cast<float4*>(&a[0]) = *reinterpret_cast<const float4*>(&As[k][ty * 8]);
        *reinterpret_cast<float4*>(&a[4]) = *reinterpret_cast<const float4*>(&As[k][ty * 8 + 4]);
        *reinterpret_cast<float4*>(&b[0]) = *reinterpret_cast<const float4*>(&Bs[k][tx * 8]);
        *reinterpret_cast<float4*>(&b[4]) = *reinterpret_cast<const float4*>(&Bs[k][tx * 8 + 4]);
        #pragma unroll
        for (int i = 0; i < 8; i++)
            #pragma unroll
            for (int j = 0; j < 8; j++)
                acc[i][j] = fmaf(a[i], b[j], acc[i][j]);
    }
}

// ---------------- RoPE cos/sin tables ----------------
__global__ void k_rope_tab() {
    int t = blockIdx.x;
    for (int n = threadIdx.x; n < NN_; n += 256) {
        float q    = (float)(n & ~1);
        // THETA = 2^16 ; THETA^(q/N) = exp2(16*q/2048) = exp2(q/128)
        float freq = exp2f(-q * (1.0f / 128.0f)) * INV_2PI_;
        float ph   = fmodf((float)t * freq, 1.0f) * TWO_PI_;
        float s, c;
        sincosf(ph, &s, &c);
        g_pc[(size_t)t * NN_ + n] = c;
        g_ps[(size_t)t * NN_ + n] = s;
    }
}

// ---------------- x = LN(embed[idx]) ----------------
__global__ void k_embed_ln(const int* __restrict__ idx, const float* __restrict__ embed) {
    int t = blockIdx.x, d = threadIdx.x;
    float v   = embed[(size_t)idx[t] * D_ + d];
    float m   = blk_sum256(v) * (1.0f / D_);
    float dv  = v - m;
    float var = blk_sum256(dv * dv) * (1.0f / D_);
    g_x[(size_t)t * D_ + d] = dv * rsqrtf(var + EPS_);
}

// ---------------- enc GEMM: MODE 1: xs=relu(x@enc), qr=rope(xs)
// ----------------           MODE 4: xy = relu(yKV@encv) * xs  (into g_qr)
template <int MODE>
__global__ void __launch_bounds__(256) k_enc(const float* __restrict__ W) {
    __shared__ float As[16][128];
    __shared__ float Bs[16][128];
    const int h = blockIdx.z;
    const int tid = threadIdx.x, tx = tid & 15, ty = tid >> 4;
    const float* Abase = (MODE == 1) ? g_x : (g_ykv + (size_t)h * T_ * D_);
    const float* Ap = Abase + (size_t)blockIdx.y * 128 * D_;
    const float* Bp = W + (size_t)h * D_ * NN_ + blockIdx.x * 128;
    float acc[8][8];
    #pragma unroll
    for (int i = 0; i < 8; i++)
        #pragma unroll
        for (int j = 0; j < 8; j++) acc[i][j] = 0.f;
    for (int kt = 0; kt < D_; kt += 16) {
        load_tileT(As, Ap, D_, kt);
        load_tileB(Bs, Bp, NN_, kt);
        __syncthreads();
        gemm_compute(As, Bs, acc, tx, ty);
        __syncthreads();
    }
    int t0 = blockIdx.y * 128 + ty * 8;
    int n0 = blockIdx.x * 128 + tx * 8;
    size_t hbase = (size_t)h * T_ * NN_;
    #pragma unroll
    for (int i = 0; i < 8; i++) {
        int t = t0 + i;
        size_t rb = hbase + (size_t)t * NN_ + n0;
        if (MODE == 1) {
            size_t pb = (size_t)t * NN_ + n0;
            #pragma unroll
            for (int jj = 0; jj < 4; jj++) {
                float v0 = fmaxf(acc[i][2 * jj], 0.f);
                float v1 = fmaxf(acc[i][2 * jj + 1], 0.f);
                g_xs[rb + 2 * jj]     = v0;
                g_xs[rb + 2 * jj + 1] = v1;
                float c0 = g_pc[pb + 2 * jj],     s0 = g_ps[pb + 2 * jj];
                float c1 = g_pc[pb + 2 * jj + 1], s1 = g_ps[pb + 2 * jj + 1];
                g_qr[rb + 2 * jj]     = v0 * c0 - v1 * s0;  // v*pc + (-v_odd)*ps
                g_qr[rb + 2 * jj + 1] = v1 * c1 + v0 * s1;  // v*pc + ( v_even)*ps
            }
        } else {
            #pragma unroll
            for (int j = 0; j < 8; j++)
                g_qr[rb + j] = fmaxf(acc[i][j], 0.f) * g_xs[rb + j];
        }
    }
}

// ---------------- scores = tril(qr @ qr^T, k=-1) ; upper blocks never written/read ----------------
__global__ void __launch_bounds__(256) k_scores() {
    int bx = blockIdx.x, by = blockIdx.y, h = blockIdx.z;
    if (bx > by) return;  // strictly-upper blocks unused
    __shared__ float As[16][128];
    __shared__ float Bs[16][128];
    const int tid = threadIdx.x, tx = tid & 15, ty = tid >> 4;
    const float* base = g_qr + (size_t)h * T_ * NN_;
    const float* Ap = base + (size_t)by * 128 * NN_;
    const float* Bp = base + (size_t)bx * 128 * NN_;
    float acc[8][8];
    #pragma unroll
    for (int i = 0; i < 8; i++)
        #pragma unroll
        for (int j = 0; j < 8; j++) acc[i][j] = 0.f;
    for (int kt = 0; kt < NN_; kt += 16) {
        load_tileT(As, Ap, NN_, kt);
        load_tileT(Bs, Bp, NN_, kt);   // B = qr rows (u), K-contiguous -> transposed tile
        __syncthreads();
        gemm_compute(As, Bs, acc, tx, ty);
        __syncthreads();
    }
    int t0 = by * 128 + ty * 8;
    int u0 = bx * 128 + tx * 8;
    float* Cb = g_sc + (size_t)h * T_ * T_;
    if (bx != by) {
        #pragma unroll
        for (int i = 0; i < 8; i++) {
            float* cp = &Cb[(size_t)(t0 + i) * T_ + u0];
            *reinterpret_cast<float4*>(cp)     = *reinterpret_cast<float4*>(&acc[i][0]);
            *reinterpret_cast<float4*>(cp + 4) = *reinterpret_cast<float4*>(&acc[i][4]);
        }
    } else {
        #pragma unroll
        for (int i = 0; i < 8; i++) {
            int t = t0 + i;
            #pragma unroll
            for (int j = 0; j < 8; j++) {
                int u = u0 + j;
                Cb[(size_t)t * T_ + u] = (u < t) ? acc[i][j] : 0.f;  // strict lower
            }
        }
    }
}

// ---------------- yKV_raw = scores @ x   (K limited by causality) ----------------
__global__ void __launch_bounds__(256) k_ykv() {
    __shared__ float As[16][128];
    __shared__ float Bs[16][128];
    const int h = blockIdx.z;
    const int tid = threadIdx.x, tx = tid & 15, ty = tid >> 4;
    const float* Ap = g_sc + (size_t)h * T_ * T_ + (size_t)blockIdx.y * 128 * T_;
    const float* Bp = g_x + blockIdx.x * 128;
    const int Kend = (blockIdx.y + 1) * 128;   // rows t need only u < t
    float acc[8][8];
    #pragma unroll
    for (int i = 0; i < 8; i++)
        #pragma unroll
        for (int j = 0; j < 8; j++) acc[i][j] = 0.f;
    for (int kt = 0; kt < Kend; kt += 16) {
        load_tileT(As, Ap, T_, kt);
        load_tileB(Bs, Bp, D_, kt);
        __syncthreads();
        gemm_compute(As, Bs, acc, tx, ty);
        __syncthreads();
    }
    int t0 = blockIdx.y * 128 + ty * 8;
    int c0 = blockIdx.x * 128 + tx * 8;
    float* Cb = g_ykv + (size_t)h * T_ * D_;
    #pragma unroll
    for (int i = 0; i < 8; i++) {
        float* cp = &Cb[(size_t)(t0 + i) * D_ + c0];
        *reinterpret_cast<float4*>(cp)     = *reinterpret_cast<float4*>(&acc[i][0]);
        *reinterpret_cast<float4*>(cp + 4) = *reinterpret_cast<float4*>(&acc[i][4]);
    }
}

// ---------------- in-place LN of yKV rows ----------------
__global__ void k_ln_ykv() {
    size_t r = blockIdx.x;
    int d = threadIdx.x;
    float v   = g_ykv[r * D_ + d];
    float m   = blk_sum256(v) * (1.0f / D_);
    float dv  = v - m;
    float var = blk_sum256(dv * dv) * (1.0f / D_);
    g_ykv[r * D_ + d] = dv * rsqrtf(var + EPS_);
}

// ---------------- decoder GEMM, deterministic split-K=8: partials into g_part ----------------
__global__ void __launch_bounds__(256) k_dec(const float* __restrict__ dec) {
    __shared__ float As[16][128];
    __shared__ float Bs[16][128];
    const int seg = blockIdx.z;
    const int k0 = seg * 1024;
    const int tid = threadIdx.x, tx = tid & 15, ty = tid >> 4;
    const int t_base = blockIdx.y * 128;
    const float* Bp = dec + blockIdx.x * 128;
    float acc[8][8];
    #pragma unroll
    for (int i = 0; i < 8; i++)
        #pragma unroll
        for (int j = 0; j < 8; j++) acc[i][j] = 0.f;
    for (int kt = k0; kt < k0 + 1024; kt += 16) {
        // A(t,k) = xy[h= k>>11][t][k & 2047], xy lives in g_qr
        #pragma unroll
        for (int it = 0; it < 2; ++it) {
            int q = tid + it * 256;
            int r = q >> 2;
            int c4 = (q & 3) * 4;
            int k = kt + c4;
            const float* p = g_qr + ((size_t)(k >> 11)) * T_ * NN_
                                  + (size_t)(t_base + r) * NN_ + (k & (NN_ - 1));
            float4 v = *reinterpret_cast<const float4*>(p);
            As[c4 + 0][r] = v.x; As[c4 + 1][r] = v.y; As[c4 + 2][r] = v.z; As[c4 + 3][r] = v.w;
        }
        load_tileB(Bs, Bp, D_, kt);
        __syncthreads();
        gemm_compute(As, Bs, acc, tx, ty);
        __syncthreads();
    }
    int t0 = t_base + ty * 8;
    int c0 = blockIdx.x * 128 + tx * 8;
    float* P = g_part + (size_t)seg * T_ * D_;
    #pragma unroll
    for (int i = 0; i < 8; i++) {
        float* cp = &P[(size_t)(t0 + i) * D_ + c0];
        *reinterpret_cast<float4*>(cp)     = *reinterpret_cast<float4*>(&acc[i][0]);
        *reinterpret_cast<float4*>(cp + 4) = *reinterpret_cast<float4*>(&acc[i][4]);
    }
}

// ---------------- x = LN(x + LN(sum_partials)) ----------------
__global__ void k_ln2() {
    int t = blockIdx.x, d = threadIdx.x;
    size_t o = (size_t)t * D_ + d;
    float y = 0.f;
    #pragma unroll
    for (int s = 0; s < 8; s++) y += g_part[(size_t)s * T_ * D_ + o];
    float m1 = blk_sum256(y) * (1.0f / D_);
    float dy = y - m1;
    float v1 = blk_sum256(dy * dy) * (1.0f / D_);
    float u  = dy * rsqrtf(v1 + EPS_);
    float w  = g_x[o] + u;
    float m2 = blk_sum256(w) * (1.0f / D_);
    float dw = w - m2;
    float v2 = blk_sum256(dw * dw) * (1.0f / D_);
    g_x[o] = dw * rsqrtf(v2 + EPS_);
}

// ---------------- logits = x @ lm_head ----------------
__global__ void __launch_bounds__(256) k_logits(const float* __restrict__ lmh, float* __restrict__ out) {
    __shared__ float As[16][128];
    __shared__ float Bs[16][128];
    const int tid = threadIdx.x, tx = tid & 15, ty = tid >> 4;
    const float* Ap = g_x + (size_t)blockIdx.y * 128 * D_;
    const float* Bp = lmh + blockIdx.x * 128;
    float acc[8][8];
    #pragma unroll
    for (int i = 0; i < 8; i++)
        #pragma unroll
        for (int j = 0; j < 8; j++) acc[i][j] = 0.f;
    for (int kt = 0; kt < D_; kt += 16) {
        load_tileT(As, Ap, D_, kt);
        load_tileB(Bs, Bp, VOCAB_, kt);
        __syncthreads();
        gemm_compute(As, Bs, acc, tx, ty);
        __syncthreads();
    }
    int t0 = blockIdx.y * 128 + ty * 8;
    int c0 = blockIdx.x * 128 + tx * 8;
    #pragma unroll
    for (int i = 0; i < 8; i++) {
        float* cp = &out[(size_t)(t0 + i) * VOCAB_ + c0];
        *reinterpret_cast<float4*>(cp)     = *reinterpret_cast<float4*>(&acc[i][0]);
        *reinterpret_cast<float4*>(cp + 4) = *reinterpret_cast<float4*>(&acc[i][4]);
    }
}

// ---------------- host launch ----------------
extern "C" void kernel_launch(void* const* d_in, const int* in_sizes, int n_in,
                              void* d_out, int out_size) {
    (void)in_sizes; (void)n_in; (void)out_size;
    const int*   idx   = (const int*)d_in[0];
    const float* embed = (const float*)d_in[1];
    const float* enc   = (const float*)d_in[2];
    const float* encv  = (const float*)d_in[3];
    const float* dec   = (const float*)d_in[4];
    const float* lmh   = (const float*)d_in[5];
    float* out = (float*)d_out;

    k_rope_tab<<<T_, 256>>>();
    k_embed_ln<<<T_, 256>>>(idx, embed);

    for (int l = 0; l < NL_; ++l) {
        k_enc<1><<<dim3(16, 16, NH_), 256>>>(enc);
        k_scores<<<dim3(16, 16, NH_), 256>>>();
        k_ykv<<<dim3(2, 16, NH_), 256>>>();
        k_ln_ykv<<<NH_ * T_, 256>>>();
        k_enc<4><<<dim3(16, 16, NH_), 256>>>(encv);
        k_dec<<<dim3(2, 16, 8), 256>>>(dec);
        k_ln2<<<T_, 256>>>();
    }
    k_logits<<<dim3(2, 16, 1), 256>>>(lmh, out);
}

// round 5
// speedup vs baseline: 1.0759x; 1.0759x over previous
#include <cuda_runtime.h>
#include <cstdint>
#include <cstddef>

#define T_   2048
#define D_   256
#define NN_  2048
#define NH_  4
#define NL_  6
#define VOCAB_ 256
#define EPS_ 1e-5f
#define TWO_PI_ 6.283185307179586f
#define INV_2PI_ 0.15915494309189535f

// ---------------- scratch (device globals; no allocations) ----------------
__device__ float g_x   [(size_t)T_ * D_];          //  2 MB  current hidden (T,D)
__device__ float g_pc  [(size_t)T_ * NN_];         // 16 MB  rope cos table
__device__ float g_ps  [(size_t)T_ * NN_];         // 16 MB  rope sin table
__device__ float g_xs  [(size_t)NH_ * T_ * NN_];   // 64 MB  x_sparse
__device__ float g_qr  [(size_t)NH_ * T_ * NN_];   // 64 MB  rope(x_sparse), later xy
__device__ float g_sc  [(size_t)NH_ * T_ * T_];    // 64 MB  scores (lower triangle valid)
__device__ float g_ykv [(size_t)NH_ * T_ * D_];    //  8 MB  yKV
__device__ float g_part[(size_t)8  * T_ * D_];     // 16 MB  split-K partials for decoder GEMM

// ---------------- helpers ----------------
__device__ __forceinline__ float tf32r(float v) {
    uint32_t r;
    asm("cvt.rna.tf32.f32 %0, %1;" : "=r"(r) : "f"(v));
    return __uint_as_float(r);
}
__device__ __forceinline__ uint32_t fu(float v) { return __float_as_uint(v); }

__device__ __forceinline__ void mma8(float* c,
                                     uint32_t a0, uint32_t a1, uint32_t a2, uint32_t a3,
                                     uint32_t b0, uint32_t b1) {
    asm volatile(
        "mma.sync.aligned.m16n8k8.row.col.f32.tf32.tf32.f32 "
        "{%0,%1,%2,%3},{%4,%5,%6,%7},{%8,%9},{%0,%1,%2,%3};"
        : "+f"(c[0]), "+f"(c[1]), "+f"(c[2]), "+f"(c[3])
        : "r"(a0), "r"(a1), "r"(a2), "r"(a3), "r"(b0), "r"(b1));
}

// ---------------- block reduction over 256 threads ----------------
__device__ __forceinline__ float blk_sum256(float v) {
    __shared__ float sb[8];
    #pragma unroll
    for (int o = 16; o; o >>= 1) v += __shfl_xor_sync(0xffffffffu, v, o);
    int tid = threadIdx.x;
    if ((tid & 31) == 0) sb[tid >> 5] = v;
    __syncthreads();
    if (tid == 0) {
        float s = 0.f;
        #pragma unroll
        for (int i = 0; i < 8; i++) s += sb[i];
        sb[0] = s;
    }
    __syncthreads();
    float r = sb[0];
    __syncthreads();
    return r;
}

// ---------------- SMEM tile loaders with tf32 hi/lo split ----------------
// stride 136 floats: fragment loads conflict-free (8*tig+grp spans 32 banks)
#define LDST 136

// A-style: src row-major [row][k], ld; store transposed dst[k][row] (hi/lo)
__device__ __forceinline__ void ld_T(float (&dh)[16][LDST], float (&dl)[16][LDST],
                                     const float* __restrict__ src, int ld, int kbase) {
    int tid = threadIdx.x;
    #pragma unroll
    for (int it = 0; it < 2; ++it) {
        int q = tid + it * 256;
        int r = q >> 2;
        int c = (q & 3) * 4;
        float4 v = *reinterpret_cast<const float4*>(src + (size_t)r * ld + kbase + c);
        float h;
        h = tf32r(v.x); dh[c + 0][r] = h; dl[c + 0][r] = v.x - h;
        h = tf32r(v.y); dh[c + 1][r] = h; dl[c + 1][r] = v.y - h;
        h = tf32r(v.z); dh[c + 2][r] = h; dl[c + 2][r] = v.z - h;
        h = tf32r(v.w); dh[c + 3][r] = h; dl[c + 3][r] = v.w - h;
    }
}
// B-style: src row-major [k][n] (already offset to n0), ld; store dst[k][n] (hi/lo)
__device__ __forceinline__ void ld_B(float (&dh)[16][LDST], float (&dl)[16][LDST],
                                     const float* __restrict__ src, int ld, int kbase) {
    int tid = threadIdx.x;
    #pragma unroll
    for (int it = 0; it < 2; ++it) {
        int q = tid + it * 256;
        int r = q >> 5;
        int c = (q & 31) * 4;
        float4 v = *reinterpret_cast<const float4*>(src + (size_t)(kbase + r) * ld + c);
        float4 hv, lv;
        hv.x = tf32r(v.x); lv.x = v.x - hv.x;
        hv.y = tf32r(v.y); lv.y = v.y - hv.y;
        hv.z = tf32r(v.z); lv.z = v.z - hv.z;
        hv.w = tf32r(v.w); lv.w = v.w - hv.w;
        *reinterpret_cast<float4*>(&dh[r][c]) = hv;
        *reinterpret_cast<float4*>(&dl[r][c]) = lv;
    }
}

// ---------------- 128x128x16 tile compute via tf32 3-term split ----------------
__device__ __forceinline__ void mma_tile(const float (&Ah)[16][LDST], const float (&Al)[16][LDST],
                                         const float (&Bh)[16][LDST], const float (&Bl)[16][LDST],
                                         float (&acc)[4][4][4], int wm, int wn, int grp, int tig) {
    #pragma unroll
    for (int ks = 0; ks < 16; ks += 8) {
        float ah[4][4], al[4][4];
        #pragma unroll
        for (int mi = 0; mi < 4; mi++) {
            int r0 = wm + mi * 16 + grp;
            ah[mi][0] = Ah[ks + tig][r0];     ah[mi][1] = Ah[ks + tig][r0 + 8];
            ah[mi][2] = Ah[ks + tig + 4][r0]; ah[mi][3] = Ah[ks + tig + 4][r0 + 8];
            al[mi][0] = Al[ks + tig][r0];     al[mi][1] = Al[ks + tig][r0 + 8];
            al[mi][2] = Al[ks + tig + 4][r0]; al[mi][3] = Al[ks + tig + 4][r0 + 8];
        }
        #pragma unroll
        for (int ni = 0; ni < 4; ni++) {
            int c0 = wn + ni * 8 + grp;
            uint32_t bh0 = fu(Bh[ks + tig][c0]), bh1 = fu(Bh[ks + tig + 4][c0]);
            uint32_t bl0 = fu(Bl[ks + tig][c0]), bl1 = fu(Bl[ks + tig + 4][c0]);
            #pragma unroll
            for (int mi = 0; mi < 4; mi++) {
                uint32_t a0 = fu(ah[mi][0]), a1 = fu(ah[mi][1]),
                         a2 = fu(ah[mi][2]), a3 = fu(ah[mi][3]);
                mma8(acc[mi][ni], a0, a1, a2, a3, bh0, bh1);
                mma8(acc[mi][ni], a0, a1, a2, a3, bl0, bl1);
                mma8(acc[mi][ni], fu(al[mi][0]), fu(al[mi][1]),
                                  fu(al[mi][2]), fu(al[mi][3]), bh0, bh1);
            }
        }
    }
}

#define WARP_IDS                                   \
    const int tid = threadIdx.x;                   \
    const int lane = tid & 31, warp = tid >> 5;    \
    const int grp = lane >> 2, tig = lane & 3;     \
    const int wm = (warp >> 2) * 64, wn = (warp & 3) * 32;

#define ZERO_ACC float acc[4][4][4];               \
    _Pragma("unroll") for (int i = 0; i < 4; i++)  \
    _Pragma("unroll") for (int j = 0; j < 4; j++)  \
    _Pragma("unroll") for (int r = 0; r < 4; r++) acc[i][j][r] = 0.f;

// plain C store: Cb row-major [row][ldc]
__device__ __forceinline__ void store_plain(float* __restrict__ Cb, int ldc,
                                            int t_blk, int c_blk, const float (&acc)[4][4][4],
                                            int wm, int wn, int grp, int tig) {
    #pragma unroll
    for (int mi = 0; mi < 4; mi++)
        #pragma unroll
        for (int ni = 0; ni < 4; ni++) {
            int col = c_blk + wn + ni * 8 + 2 * tig;
            #pragma unroll
            for (int h = 0; h < 2; h++) {
                int row = t_blk + wm + mi * 16 + grp + 8 * h;
                float2 v = make_float2(acc[mi][ni][2 * h], acc[mi][ni][2 * h + 1]);
                *reinterpret_cast<float2*>(&Cb[(size_t)row * ldc + col]) = v;
            }
        }
}

// ---------------- RoPE cos/sin tables ----------------
__global__ void k_rope_tab() {
    int t = blockIdx.x;
    for (int n = threadIdx.x; n < NN_; n += 256) {
        float q    = (float)(n & ~1);
        float freq = exp2f(-q * (1.0f / 128.0f)) * INV_2PI_;   // THETA = 2^16
        float ph   = fmodf((float)t * freq, 1.0f) * TWO_PI_;
        float s, c;
        sincosf(ph, &s, &c);
        g_pc[(size_t)t * NN_ + n] = c;
        g_ps[(size_t)t * NN_ + n] = s;
    }
}

// ---------------- x = LN(embed[idx]) ----------------
__global__ void k_embed_ln(const int* __restrict__ idx, const float* __restrict__ embed) {
    int t = blockIdx.x, d = threadIdx.x;
    float v   = embed[(size_t)idx[t] * D_ + d];
    float m   = blk_sum256(v) * (1.0f / D_);
    float dv  = v - m;
    float var = blk_sum256(dv * dv) * (1.0f / D_);
    g_x[(size_t)t * D_ + d] = dv * rsqrtf(var + EPS_);
}

// ---------------- enc GEMM: MODE 1: xs=relu(x@enc), qr=rope(xs)
// ----------------           MODE 4: xy = relu(yKV@encv) * xs  (into g_qr)
template <int MODE>
__global__ void __launch_bounds__(256) k_enc(const float* __restrict__ W) {
    __shared__ float Ah[16][LDST], Al[16][LDST], Bh[16][LDST], Bl[16][LDST];
    const int h = blockIdx.z;
    WARP_IDS
    const float* Abase = (MODE == 1) ? g_x : (g_ykv + (size_t)h * T_ * D_);
    const float* Ap = Abase + (size_t)blockIdx.y * 128 * D_;
    const float* Bp = W + (size_t)h * D_ * NN_ + blockIdx.x * 128;
    ZERO_ACC
    for (int kt = 0; kt < D_; kt += 16) {
        ld_T(Ah, Al, Ap, D_, kt);
        ld_B(Bh, Bl, Bp, NN_, kt);
        __syncthreads();
        mma_tile(Ah, Al, Bh, Bl, acc, wm, wn, grp, tig);
        __syncthreads();
    }
    const int t_blk = blockIdx.y * 128, n_blk = blockIdx.x * 128;
    const size_t hbase = (size_t)h * T_ * NN_;
    #pragma unroll
    for (int mi = 0; mi < 4; mi++)
        #pragma unroll
        for (int ni = 0; ni < 4; ni++) {
            int C0 = n_blk + wn + ni * 8 + 2 * tig;
            #pragma unroll
            for (int hh = 0; hh < 2; hh++) {
                int t = t_blk + wm + mi * 16 + grp + 8 * hh;
                float v0 = fmaxf(acc[mi][ni][2 * hh], 0.f);
                float v1 = fmaxf(acc[mi][ni][2 * hh + 1], 0.f);
                size_t rb = hbase + (size_t)t * NN_ + C0;
                if (MODE == 1) {
                    *reinterpret_cast<float2*>(&g_xs[rb]) = make_float2(v0, v1);
                    float2 pc = *reinterpret_cast<const float2*>(&g_pc[(size_t)t * NN_ + C0]);
                    float2 ps = *reinterpret_cast<const float2*>(&g_ps[(size_t)t * NN_ + C0]);
                    float q0 = v0 * pc.x - v1 * ps.x;   // even: v*pc - v_odd*ps
                    float q1 = v1 * pc.y + v0 * ps.y;   // odd:  v*pc + v_even*ps
                    *reinterpret_cast<float2*>(&g_qr[rb]) = make_float2(q0, q1);
                } else {
                    float2 xs = *reinterpret_cast<const float2*>(&g_xs[rb]);
                    *reinterpret_cast<float2*>(&g_qr[rb]) = make_float2(v0 * xs.x, v1 * xs.y);
                }
            }
        }
}

// ---------------- scores = tril(qr @ qr^T, k=-1) ----------------
__global__ void __launch_bounds__(256) k_scores() {
    int bx = blockIdx.x, by = blockIdx.y, hh = blockIdx.z;
    if (bx > by) return;
    __shared__ float Ah[16][LDST], Al[16][LDST], Bh[16][LDST], Bl[16][LDST];
    WARP_IDS
    const float* base = g_qr + (size_t)hh * T_ * NN_;
    const float* Ap = base + (size_t)by * 128 * NN_;
    const float* Bp = base + (size_t)bx * 128 * NN_;
    ZERO_ACC
    for (int kt = 0; kt < NN_; kt += 16) {
        ld_T(Ah, Al, Ap, NN_, kt);
        ld_T(Bh, Bl, Bp, NN_, kt);    // B rows are u-rows of qr (K contiguous)
        __syncthreads();
        mma_tile(Ah, Al, Bh, Bl, acc, wm, wn, grp, tig);
        __syncthreads();
    }
    float* Cb = g_sc + (size_t)hh * T_ * T_;
    int t_blk = by * 128, u_blk = bx * 128;
    if (bx != by) {
        store_plain(Cb, T_, t_blk, u_blk, acc, wm, wn, grp, tig);
    } else {
        #pragma unroll
        for (int mi = 0; mi < 4; mi++)
            #pragma unroll
            for (int ni = 0; ni < 4; ni++) {
                int C0 = u_blk + wn + ni * 8 + 2 * tig;
                #pragma unroll
                for (int h2 = 0; h2 < 2; h2++) {
                    int t = t_blk + wm + mi * 16 + grp + 8 * h2;
                    float v0 = (C0     < t) ? acc[mi][ni][2 * h2]     : 0.f;
                    float v1 = (C0 + 1 < t) ? acc[mi][ni][2 * h2 + 1] : 0.f;
                    *reinterpret_cast<float2*>(&Cb[(size_t)t * T_ + C0]) = make_float2(v0, v1);
                }
            }
    }
}

// ---------------- yKV_raw = scores @ x   (K limited by causality) ----------------
__global__ void __launch_bounds__(256) k_ykv() {
    __shared__ float Ah[16][LDST], Al[16][LDST], Bh[16][LDST], Bl[16][LDST];
    const int h = blockIdx.z;
    WARP_IDS
    const float* Ap = g_sc + (size_t)h * T_ * T_ + (size_t)blockIdx.y * 128 * T_;
    const float* Bp = g_x + blockIdx.x * 128;
    const int Kend = (blockIdx.y + 1) * 128;
    ZERO_ACC
    for (int kt = 0; kt < Kend; kt += 16) {
        ld_T(Ah, Al, Ap, T_, kt);
        ld_B(Bh, Bl, Bp, D_, kt);
        __syncthreads();
        mma_tile(Ah, Al, Bh, Bl, acc, wm, wn, grp, tig);
        __syncthreads();
    }
    store_plain(g_ykv + (size_t)h * T_ * D_, D_, blockIdx.y * 128, blockIdx.x * 128,
                acc, wm, wn, grp, tig);
}

// ---------------- in-place LN of yKV rows ----------------
__global__ void k_ln_ykv() {
    size_t r = blockIdx.x;
    int d = threadIdx.x;
    float v   = g_ykv[r * D_ + d];
    float m   = blk_sum256(v) * (1.0f / D_);
    float dv  = v - m;
    float var = blk_sum256(dv * dv) * (1.0f / D_);
    g_ykv[r * D_ + d] = dv * rsqrtf(var + EPS_);
}

// ---------------- decoder GEMM, split-K=8 ----------------
__global__ void __launch_bounds__(256) k_dec(const float* __restrict__ dec) {
    __shared__ float Ah[16][LDST], Al[16][LDST], Bh[16][LDST], Bl[16][LDST];
    const int seg = blockIdx.z;
    const int k0 = seg * 1024;
    WARP_IDS
    const int t_base = blockIdx.y * 128;
    const float* Bp = dec + blockIdx.x * 128;
    ZERO_ACC
    for (int kt = k0; kt < k0 + 1024; kt += 16) {
        // A(t,k) = xy[h = k>>11][t][k & 2047]; xy lives in g_qr
        #pragma unroll
        for (int it = 0; it < 2; ++it) {
            int q = tid + it * 256;
            int r = q >> 2;
            int c4 = (q & 3) * 4;
            int k = kt + c4;
            const float* p = g_qr + ((size_t)(k >> 11)) * T_ * NN_
                                  + (size_t)(t_base + r) * NN_ + (k & (NN_ - 1));
            float4 v = *reinterpret_cast<const float4*>(p);
            float hv;
            hv = tf32r(v.x); Ah[c4 + 0][r] = hv; Al[c4 + 0][r] = v.x - hv;
            hv = tf32r(v.y); Ah[c4 + 1][r] = hv; Al[c4 + 1][r] = v.y - hv;
            hv = tf32r(v.z); Ah[c4 + 2][r] = hv; Al[c4 + 2][r] = v.z - hv;
            hv = tf32r(v.w); Ah[c4 + 3][r] = hv; Al[c4 + 3][r] = v.w - hv;
        }
        ld_B(Bh, Bl, Bp, D_, kt);
        __syncthreads();
        mma_tile(Ah, Al, Bh, Bl, acc, wm, wn, grp, tig);
        __syncthreads();
    }
    store_plain(g_part + (size_t)seg * T_ * D_, D_, t_base, blockIdx.x * 128,
                acc, wm, wn, grp, tig);
}

// ---------------- x = LN(x + LN(sum_partials)) ----------------
__global__ void k_ln2() {
    int t = blockIdx.x, d = threadIdx.x;
    size_t o = (size_t)t * D_ + d;
    float y = 0.f;
    #pragma unroll
    for (int s = 0; s < 8; s++) y += g_part[(size_t)s * T_ * D_ + o];
    float m1 = blk_sum256(y) * (1.0f / D_);
    float dy = y - m1;
    float v1 = blk_sum256(dy * dy) * (1.0f / D_);
    float u  = dy * rsqrtf(v1 + EPS_);
    float w  = g_x[o] + u;
    float m2 = blk_sum256(w) * (1.0f / D_);
    float dw = w - m2;
    float v2 = blk_sum256(dw * dw) * (1.0f / D_);
    g_x[o] = dw * rsqrtf(v2 + EPS_);
}

// ---------------- logits = x @ lm_head ----------------
__global__ void __launch_bounds__(256) k_logits(const float* __restrict__ lmh, float* __restrict__ out) {
    __shared__ float Ah[16][LDST], Al[16][LDST], Bh[16][LDST], Bl[16][LDST];
    WARP_IDS
    const float* Ap = g_x + (size_t)blockIdx.y * 128 * D_;
    const float* Bp = lmh + blockIdx.x * 128;
    ZERO_ACC
    for (int kt = 0; kt < D_; kt += 16) {
        ld_T(Ah, Al, Ap, D_, kt);
        ld_B(Bh, Bl, Bp, VOCAB_, kt);
        __syncthreads();
        mma_tile(Ah, Al, Bh, Bl, acc, wm, wn, grp, tig);
        __syncthreads();
    }
    store_plain(out, VOCAB_, blockIdx.y * 128, blockIdx.x * 128, acc, wm, wn, grp, tig);
}

// ---------------- host launch ----------------
extern "C" void kernel_launch(void* const* d_in, const int* in_sizes, int n_in,
                              void* d_out, int out_size) {
    (void)in_sizes; (void)n_in; (void)out_size;
    const int*   idx   = (const int*)d_in[0];
    const float* embed = (const float*)d_in[1];
    const float* enc   = (const float*)d_in[2];
    const float* encv  = (const float*)d_in[3];
    const float* dec   = (const float*)d_in[4];
    const float* lmh   = (const float*)d_in[5];
    float* out = (float*)d_out;

    k_rope_tab<<<T_, 256>>>();
    k_embed_ln<<<T_, 256>>>(idx, embed);

    for (int l = 0; l < NL_; ++l) {
        k_enc<1><<<dim3(16, 16, NH_), 256>>>(enc);
        k_scores<<<dim3(16, 16, NH_), 256>>>();
        k_ykv<<<dim3(2, 16, NH_), 256>>>();
        k_ln_ykv<<<NH_ * T_, 256>>>();
        k_enc<4><<<dim3(16, 16, NH_), 256>>>(encv);
        k_dec<<<dim3(2, 16, 8), 256>>>(dec);
        k_ln2<<<T_, 256>>>();
    }
    k_logits<<<dim3(2, 16, 1), 256>>>(lmh, out);
}

// round 6
// speedup vs baseline: 1.9622x; 1.8238x over previous
#include <cuda_runtime.h>
#include <cuda_bf16.h>
#include <cstdint>
#include <cstddef>

#define T_    2048
#define D_    256
#define NN_   2048
#define NH_   4
#define NL_   6
#define VOCAB_ 256
#define NHN_  (NH_ * NN_)
#define EPS_  1e-5f
#define TWO_PI_ 6.283185307179586f
#define INV_2PI_ 0.15915494309189535f

typedef __nv_bfloat16 bf16;
typedef __nv_bfloat162 bf162;

// ---------------- scratch (device globals; no allocations) ----------------
__device__ float g_x   [(size_t)T_ * D_];            // fp32 hidden
__device__ float g_pc  [(size_t)T_ * NN_];           // rope cos
__device__ float g_ps  [(size_t)T_ * NN_];           // rope sin
__device__ float g_xs  [(size_t)NH_ * T_ * NN_];     // x_sparse fp32 (gating)
__device__ float g_ykv [(size_t)NH_ * T_ * D_];      // yKV raw fp32
__device__ float g_part[(size_t)8 * T_ * D_];        // split-K partials

// bf16 hi/lo operand planes (all k-contiguous row-major)
__device__ bf16 xp_h[(size_t)T_ * D_],    xp_l[(size_t)T_ * D_];     // x [T][D]
__device__ bf16 xT_h[(size_t)D_ * T_],    xT_l[(size_t)D_ * T_];     // x^T [D][T]
__device__ bf16 qr_h[(size_t)NH_ * T_ * NN_], qr_l[(size_t)NH_ * T_ * NN_]; // qr / xy
__device__ bf16 sc_h[(size_t)NH_ * T_ * T_],  sc_l[(size_t)NH_ * T_ * T_];  // scores
__device__ bf16 yp_h[(size_t)NH_ * T_ * D_],  yp_l[(size_t)NH_ * T_ * D_];  // LN(yKV)
__device__ bf16 encT_h[(size_t)NH_ * NN_ * D_], encT_l[(size_t)NH_ * NN_ * D_];
__device__ bf16 envT_h[(size_t)NH_ * NN_ * D_], envT_l[(size_t)NH_ * NN_ * D_];
__device__ bf16 decT_h[(size_t)D_ * NHN_],     decT_l[(size_t)D_ * NHN_];
__device__ bf16 lmhT_h[(size_t)VOCAB_ * D_],   lmhT_l[(size_t)VOCAB_ * D_];

// ---------------- small helpers ----------------
__device__ __forceinline__ uint32_t smem_u32(const void* p) {
    return (uint32_t)__cvta_generic_to_shared(p);
}
__device__ __forceinline__ void cpa16(uint32_t dst, const void* src) {
    asm volatile("cp.async.ca.shared.global [%0], [%1], 16;\n" :: "r"(dst), "l"(src));
}
__device__ __forceinline__ void cpa_commit() { asm volatile("cp.async.commit_group;\n"); }
template <int N>
__device__ __forceinline__ void cpa_wait() { asm volatile("cp.async.wait_group %0;\n" :: "n"(N)); }

__device__ __forceinline__ void mma16(float* c,
                                      uint32_t a0, uint32_t a1, uint32_t a2, uint32_t a3,
                                      uint32_t b0, uint32_t b1) {
    asm volatile(
        "mma.sync.aligned.m16n8k16.row.col.f32.bf16.bf16.f32 "
        "{%0,%1,%2,%3},{%4,%5,%6,%7},{%8,%9},{%0,%1,%2,%3};"
        : "+f"(c[0]), "+f"(c[1]), "+f"(c[2]), "+f"(c[3])
        : "r"(a0), "r"(a1), "r"(a2), "r"(a3), "r"(b0), "r"(b1));
}

// split fp32 -> bf16 hi + bf16 lo (pairwise store)
__device__ __forceinline__ void st_split2(bf16* H, bf16* L, size_t idx, float v0, float v1) {
    bf16 h0 = __float2bfloat16(v0), h1 = __float2bfloat16(v1);
    float r0 = v0 - __bfloat162float(h0), r1 = v1 - __bfloat162float(h1);
    bf162 hv; hv.x = h0; hv.y = h1;
    bf162 lv; lv.x = __float2bfloat16(r0); lv.y = __float2bfloat16(r1);
    *reinterpret_cast<bf162*>(H + idx) = hv;
    *reinterpret_cast<bf162*>(L + idx) = lv;
}

// ---------------- block reduction over 256 threads ----------------
__device__ __forceinline__ float blk_sum256(float v) {
    __shared__ float sb[8];
    #pragma unroll
    for (int o = 16; o; o >>= 1) v += __shfl_xor_sync(0xffffffffu, v, o);
    int tid = threadIdx.x;
    if ((tid & 31) == 0) sb[tid >> 5] = v;
    __syncthreads();
    if (tid == 0) {
        float s = 0.f;
        #pragma unroll
        for (int i = 0; i < 8; i++) s += sb[i];
        sb[0] = s;
    }
    __syncthreads();
    float r = sb[0];
    __syncthreads();
    return r;
}

// ---------------- core GEMM: 128x128 tile, K-tiles of 16, bf16 3-term ----------------
// smem stage: 4 planes (Ah, Al, Bh, Bl), each [128 rows][12 u32] (8 kpairs + pad)
#define PLANE_U32 1536               // 128 * 12
#define PLANE_B   6144               // bytes
#define STAGE_U32 (4 * PLANE_U32)

__device__ __forceinline__ void gemm_bf16(
    const bf16* __restrict__ Agh, const bf16* __restrict__ Agl, int lda,
    const bf16* __restrict__ Bgh, const bf16* __restrict__ Bgl, int ldb,
    int K, uint32_t (&sm)[2][STAGE_U32], float (&acc)[4][4][4],
    int tid, int wm, int wn, int grp, int tig)
{
    const int NT  = K >> 4;
    const int row = tid >> 1;
    const int sub = tid & 1;
    const uint32_t dby = (uint32_t)(row * 12 + sub * 4) * 4u;
    const int go = sub * 8;  // element offset within k16

    auto issue = [&](int it, int s) {
        int kb = it << 4;
        uint32_t sb = smem_u32(&sm[s][0]) + dby;
        cpa16(sb,               Agh + (size_t)row * lda + kb + go);
        cpa16(sb + PLANE_B,     Agl + (size_t)row * lda + kb + go);
        cpa16(sb + 2 * PLANE_B, Bgh + (size_t)row * ldb + kb + go);
        cpa16(sb + 3 * PLANE_B, Bgl + (size_t)row * ldb + kb + go);
        cpa_commit();
    };

    issue(0, 0);
    for (int it = 0; it < NT; ++it) {
        if (it + 1 < NT) { issue(it + 1, (it + 1) & 1); cpa_wait<1>(); }
        else             { cpa_wait<0>(); }
        __syncthreads();
        const uint32_t* S  = sm[it & 1];
        const uint32_t* Ah = S;
        const uint32_t* Al = S + PLANE_U32;
        const uint32_t* Bh = S + 2 * PLANE_U32;
        const uint32_t* Bl = S + 3 * PLANE_U32;

        uint32_t ah[4][4], al[4][4];
        #pragma unroll
        for (int mi = 0; mi < 4; mi++) {
            int r0 = (wm + mi * 16 + grp) * 12 + tig;
            ah[mi][0] = Ah[r0];      ah[mi][1] = Ah[r0 + 96];
            ah[mi][2] = Ah[r0 + 4];  ah[mi][3] = Ah[r0 + 100];
            al[mi][0] = Al[r0];      al[mi][1] = Al[r0 + 96];
            al[mi][2] = Al[r0 + 4];  al[mi][3] = Al[r0 + 100];
        }
        #pragma unroll
        for (int ni = 0; ni < 4; ni++) {
            int c0 = (wn + ni * 8 + grp) * 12 + tig;
            uint32_t bh0 = Bh[c0], bh1 = Bh[c0 + 4];
            uint32_t bl0 = Bl[c0], bl1 = Bl[c0 + 4];
            #pragma unroll
            for (int mi = 0; mi < 4; mi++) {
                mma16(acc[mi][ni], ah[mi][0], ah[mi][1], ah[mi][2], ah[mi][3], bh0, bh1);
                mma16(acc[mi][ni], al[mi][0], al[mi][1], al[mi][2], al[mi][3], bh0, bh1);
                mma16(acc[mi][ni], ah[mi][0], ah[mi][1], ah[mi][2], ah[mi][3], bl0, bl1);
            }
        }
        __syncthreads();
    }
}

#define WARP_IDS                                   \
    const int tid = threadIdx.x;                   \
    const int lane = tid & 31, warp = tid >> 5;    \
    const int grp = lane >> 2, tig = lane & 3;     \
    const int wm = (warp >> 2) * 64, wn = (warp & 3) * 32;

#define ZERO_ACC float acc[4][4][4];               \
    _Pragma("unroll") for (int i = 0; i < 4; i++)  \
    _Pragma("unroll") for (int j = 0; j < 4; j++)  \
    _Pragma("unroll") for (int r = 0; r < 4; r++) acc[i][j][r] = 0.f;

// plain fp32 store of the 128x128 tile
__device__ __forceinline__ void store_plain(float* __restrict__ Cb, int ldc,
                                            int t_blk, int c_blk, const float (&acc)[4][4][4],
                                            int wm, int wn, int grp, int tig) {
    #pragma unroll
    for (int mi = 0; mi < 4; mi++)
        #pragma unroll
        for (int ni = 0; ni < 4; ni++) {
            int col = c_blk + wn + ni * 8 + 2 * tig;
            #pragma unroll
            for (int h = 0; h < 2; h++) {
                int row = t_blk + wm + mi * 16 + grp + 8 * h;
                float2 v = make_float2(acc[mi][ni][2 * h], acc[mi][ni][2 * h + 1]);
                *reinterpret_cast<float2*>(&Cb[(size_t)row * ldc + col]) = v;
            }
        }
}

// ---------------- prep: transpose fp32 [R][C] -> bf16 hi/lo planes [C][R] ----------------
__global__ void k_tsplit(const float* __restrict__ src, bf16* __restrict__ H,
                         bf16* __restrict__ L, int R, int C) {
    __shared__ float s[32][33];
    size_t zo  = (size_t)blockIdx.z * R * C;
    int c0 = blockIdx.x * 32, r0 = blockIdx.y * 32;
    #pragma unroll
    for (int i = 0; i < 4; i++) {
        int r = r0 + threadIdx.y + i * 8;
        s[threadIdx.y + i * 8][threadIdx.x] = src[zo + (size_t)r * C + c0 + threadIdx.x];
    }
    __syncthreads();
    size_t zo2 = (size_t)blockIdx.z * C * R;
    #pragma unroll
    for (int i = 0; i < 4; i++) {
        int c = c0 + threadIdx.y + i * 8;
        float v = s[threadIdx.x][threadIdx.y + i * 8];
        bf16 h = __float2bfloat16(v);
        size_t o = zo2 + (size_t)c * R + r0 + threadIdx.x;
        H[o] = h;
        L[o] = __float2bfloat16(v - __bfloat162float(h));
    }
}

// ---------------- RoPE cos/sin tables ----------------
__global__ void k_rope_tab() {
    int t = blockIdx.x;
    for (int n = threadIdx.x; n < NN_; n += 256) {
        float q    = (float)(n & ~1);
        float freq = exp2f(-q * (1.0f / 128.0f)) * INV_2PI_;   // THETA = 2^16
        float ph   = fmodf((float)t * freq, 1.0f) * TWO_PI_;
        float s, c;
        sincosf(ph, &s, &c);
        g_pc[(size_t)t * NN_ + n] = c;
        g_ps[(size_t)t * NN_ + n] = s;
    }
}

// ---------------- x = LN(embed[idx]); write fp32 + planes + transposed planes ----------------
__global__ void k_embed_ln(const int* __restrict__ idx, const float* __restrict__ embed) {
    int t = blockIdx.x, d = threadIdx.x;
    float v   = embed[(size_t)idx[t] * D_ + d];
    float m   = blk_sum256(v) * (1.0f / D_);
    float dv  = v - m;
    float var = blk_sum256(dv * dv) * (1.0f / D_);
    float x = dv * rsqrtf(var + EPS_);
    size_t o = (size_t)t * D_ + d;
    g_x[o] = x;
    bf16 h = __float2bfloat16(x);
    bf16 l = __float2bfloat16(x - __bfloat162float(h));
    xp_h[o] = h; xp_l[o] = l;
    size_t ot = (size_t)d * T_ + t;
    xT_h[ot] = h; xT_l[ot] = l;
}

// ---------------- enc GEMM: MODE 1: xs=relu(x@enc), qr=rope(xs)
// ----------------           MODE 4: xy = relu(yKV@encv) * xs (into qr planes)
template <int MODE>
__global__ void __launch_bounds__(256, 2) k_enc() {
    __shared__ uint32_t sm[2][STAGE_U32];
    WARP_IDS
    const int h = blockIdx.z;
    const int t_blk = blockIdx.y * 128, n_blk = blockIdx.x * 128;
    const bf16 *Agh, *Agl, *Bgh, *Bgl;
    if (MODE == 1) {
        Agh = xp_h + (size_t)t_blk * D_;
        Agl = xp_l + (size_t)t_blk * D_;
        Bgh = encT_h + ((size_t)h * NN_ + n_blk) * D_;
        Bgl = encT_l + ((size_t)h * NN_ + n_blk) * D_;
    } else {
        Agh = yp_h + ((size_t)h * T_ + t_blk) * D_;
        Agl = yp_l + ((size_t)h * T_ + t_blk) * D_;
        Bgh = envT_h + ((size_t)h * NN_ + n_blk) * D_;
        Bgl = envT_l + ((size_t)h * NN_ + n_blk) * D_;
    }
    ZERO_ACC
    gemm_bf16(Agh, Agl, D_, Bgh, Bgl, D_, D_, sm, acc, tid, wm, wn, grp, tig);

    const size_t hbase = (size_t)h * T_ * NN_;
    #pragma unroll
    for (int mi = 0; mi < 4; mi++)
        #pragma unroll
        for (int ni = 0; ni < 4; ni++) {
            int C0 = n_blk + wn + ni * 8 + 2 * tig;
            #pragma unroll
            for (int hh = 0; hh < 2; hh++) {
                int t = t_blk + wm + mi * 16 + grp + 8 * hh;
                float v0 = fmaxf(acc[mi][ni][2 * hh], 0.f);
                float v1 = fmaxf(acc[mi][ni][2 * hh + 1], 0.f);
                size_t rb = hbase + (size_t)t * NN_ + C0;
                if (MODE == 1) {
                    *reinterpret_cast<float2*>(&g_xs[rb]) = make_float2(v0, v1);
                    float2 pc = *reinterpret_cast<const float2*>(&g_pc[(size_t)t * NN_ + C0]);
                    float2 ps = *reinterpret_cast<const float2*>(&g_ps[(size_t)t * NN_ + C0]);
                    float q0 = v0 * pc.x - v1 * ps.x;
                    float q1 = v1 * pc.y + v0 * ps.y;
                    st_split2(qr_h, qr_l, rb, q0, q1);
                } else {
                    float2 xs = *reinterpret_cast<const float2*>(&g_xs[rb]);
                    st_split2(qr_h, qr_l, rb, v0 * xs.x, v1 * xs.y);
                }
            }
        }
}

// ---------------- scores = tril(qr @ qr^T, k=-1) into sc planes ----------------
__global__ void __launch_bounds__(256, 2) k_scores() {
    int bx = blockIdx.x, by = blockIdx.y, hz = blockIdx.z;
    if (bx > by) return;
    __shared__ uint32_t sm[2][STAGE_U32];
    WARP_IDS
    const bf16* Agh = qr_h + ((size_t)hz * T_ + by * 128) * NN_;
    const bf16* Agl = qr_l + ((size_t)hz * T_ + by * 128) * NN_;
    const bf16* Bgh = qr_h + ((size_t)hz * T_ + bx * 128) * NN_;
    const bf16* Bgl = qr_l + ((size_t)hz * T_ + bx * 128) * NN_;
    ZERO_ACC
    gemm_bf16(Agh, Agl, NN_, Bgh, Bgl, NN_, NN_, sm, acc, tid, wm, wn, grp, tig);

    const size_t hbase = (size_t)hz * T_ * T_;
    int t_blk = by * 128, u_blk = bx * 128;
    if (bx != by) {
        #pragma unroll
        for (int mi = 0; mi < 4; mi++)
            #pragma unroll
            for (int ni = 0; ni < 4; ni++) {
                int C0 = u_blk + wn + ni * 8 + 2 * tig;
                #pragma unroll
                for (int h2 = 0; h2 < 2; h2++) {
                    int t = t_blk + wm + mi * 16 + grp + 8 * h2;
                    st_split2(sc_h, sc_l, hbase + (size_t)t * T_ + C0,
                              acc[mi][ni][2 * h2], acc[mi][ni][2 * h2 + 1]);
                }
            }
    } else {
        #pragma unroll
        for (int mi = 0; mi < 4; mi++)
            #pragma unroll
            for (int ni = 0; ni < 4; ni++) {
                int C0 = u_blk + wn + ni * 8 + 2 * tig;
                #pragma unroll
                for (int h2 = 0; h2 < 2; h2++) {
                    int t = t_blk + wm + mi * 16 + grp + 8 * h2;
                    float v0 = (C0     < t) ? acc[mi][ni][2 * h2]     : 0.f;
                    float v1 = (C0 + 1 < t) ? acc[mi][ni][2 * h2 + 1] : 0.f;
                    st_split2(sc_h, sc_l, hbase + (size_t)t * T_ + C0, v0, v1);
                }
            }
    }
}

// ---------------- yKV_raw = scores @ x (K limited by causality) ----------------
__global__ void __launch_bounds__(256, 2) k_ykv() {
    __shared__ uint32_t sm[2][STAGE_U32];
    WARP_IDS
    const int h = blockIdx.z;
    const int Kend = (blockIdx.y + 1) * 128;
    const bf16* Agh = sc_h + ((size_t)h * T_ + blockIdx.y * 128) * T_;
    const bf16* Agl = sc_l + ((size_t)h * T_ + blockIdx.y * 128) * T_;
    const bf16* Bgh = xT_h + (size_t)blockIdx.x * 128 * T_;
    const bf16* Bgl = xT_l + (size_t)blockIdx.x * 128 * T_;
    ZERO_ACC
    gemm_bf16(Agh, Agl, T_, Bgh, Bgl, T_, Kend, sm, acc, tid, wm, wn, grp, tig);
    store_plain(g_ykv + (size_t)h * T_ * D_, D_, blockIdx.y * 128, blockIdx.x * 128,
                acc, wm, wn, grp, tig);
}

// ---------------- LN(yKV) -> planes ----------------
__global__ void k_ln_ykv() {
    size_t r = blockIdx.x;
    int d = threadIdx.x;
    float v   = g_ykv[r * D_ + d];
    float m   = blk_sum256(v) * (1.0f / D_);
    float dv  = v - m;
    float var = blk_sum256(dv * dv) * (1.0f / D_);
    float y = dv * rsqrtf(var + EPS_);
    bf16 h = __float2bfloat16(y);
    yp_h[r * D_ + d] = h;
    yp_l[r * D_ + d] = __float2bfloat16(y - __bfloat162float(h));
}

// ---------------- decoder GEMM, split-K=8 ----------------
__global__ void __launch_bounds__(256, 2) k_dec() {
    __shared__ uint32_t sm[2][STAGE_U32];
    WARP_IDS
    const int seg = blockIdx.z;
    const int h = seg >> 1;
    const int colb = (seg & 1) * 1024;
    const int t_blk = blockIdx.y * 128, c_blk = blockIdx.x * 128;
    const bf16* Agh = qr_h + ((size_t)h * T_ + t_blk) * NN_ + colb;
    const bf16* Agl = qr_l + ((size_t)h * T_ + t_blk) * NN_ + colb;
    const bf16* Bgh = decT_h + (size_t)c_blk * NHN_ + seg * 1024;
    const bf16* Bgl = decT_l + (size_t)c_blk * NHN_ + seg * 1024;
    ZERO_ACC
    gemm_bf16(Agh, Agl, NN_, Bgh, Bgl, NHN_, 1024, sm, acc, tid, wm, wn, grp, tig);
    store_plain(g_part + (size_t)seg * T_ * D_, D_, t_blk, c_blk, acc, wm, wn, grp, tig);
}

// ---------------- x = LN(x + LN(sum_partials)); refresh planes ----------------
__global__ void k_ln2() {
    int t = blockIdx.x, d = threadIdx.x;
    size_t o = (size_t)t * D_ + d;
    float y = 0.f;
    #pragma unroll
    for (int s = 0; s < 8; s++) y += g_part[(size_t)s * T_ * D_ + o];
    float m1 = blk_sum256(y) * (1.0f / D_);
    float dy = y - m1;
    float v1 = blk_sum256(dy * dy) * (1.0f / D_);
    float u  = dy * rsqrtf(v1 + EPS_);
    float w  = g_x[o] + u;
    float m2 = blk_sum256(w) * (1.0f / D_);
    float dw = w - m2;
    float v2 = blk_sum256(dw * dw) * (1.0f / D_);
    float x  = dw * rsqrtf(v2 + EPS_);
    g_x[o] = x;
    bf16 h = __float2bfloat16(x);
    bf16 l = __float2bfloat16(x - __bfloat162float(h));
    xp_h[o] = h; xp_l[o] = l;
    size_t ot = (size_t)d * T_ + t;
    xT_h[ot] = h; xT_l[ot] = l;
}

// ---------------- logits = x @ lm_head ----------------
__global__ void __launch_bounds__(256, 2) k_logits(float* __restrict__ out) {
    __shared__ uint32_t sm[2][STAGE_U32];
    WARP_IDS
    const int t_blk = blockIdx.y * 128, c_blk = blockIdx.x * 128;
    const bf16* Agh = xp_h + (size_t)t_blk * D_;
    const bf16* Agl = xp_l + (size_t)t_blk * D_;
    const bf16* Bgh = lmhT_h + (size_t)c_blk * D_;
    const bf16* Bgl = lmhT_l + (size_t)c_blk * D_;
    ZERO_ACC
    gemm_bf16(Agh, Agl, D_, Bgh, Bgl, D_, D_, sm, acc, tid, wm, wn, grp, tig);
    store_plain(out, VOCAB_, t_blk, c_blk, acc, wm, wn, grp, tig);
}

// ---------------- host launch ----------------
extern "C" void kernel_launch(void* const* d_in, const int* in_sizes, int n_in,
                              void* d_out, int out_size) {
    (void)in_sizes; (void)n_in; (void)out_size;
    const int*   idx   = (const int*)d_in[0];
    const float* embed = (const float*)d_in[1];
    const float* enc   = (const float*)d_in[2];
    const float* encv  = (const float*)d_in[3];
    const float* dec   = (const float*)d_in[4];
    const float* lmh   = (const float*)d_in[5];
    float* out = (float*)d_out;

    bf16 *p_encT_h, *p_encT_l, *p_envT_h, *p_envT_l, *p_decT_h, *p_decT_l, *p_lmhT_h, *p_lmhT_l;
    cudaGetSymbolAddress((void**)&p_encT_h, encT_h);
    cudaGetSymbolAddress((void**)&p_encT_l, encT_l);
    cudaGetSymbolAddress((void**)&p_envT_h, envT_h);
    cudaGetSymbolAddress((void**)&p_envT_l, envT_l);
    cudaGetSymbolAddress((void**)&p_decT_h, decT_h);
    cudaGetSymbolAddress((void**)&p_decT_l, decT_l);
    cudaGetSymbolAddress((void**)&p_lmhT_h, lmhT_h);
    cudaGetSymbolAddress((void**)&p_lmhT_l, lmhT_l);

    dim3 tb(32, 8);
    k_rope_tab<<<T_, 256>>>();
    k_tsplit<<<dim3(NN_ / 32, D_ / 32, NH_), tb>>>(enc,  p_encT_h, p_encT_l, D_, NN_);
    k_tsplit<<<dim3(NN_ / 32, D_ / 32, NH_), tb>>>(encv, p_envT_h, p_envT_l, D_, NN_);
    k_tsplit<<<dim3(D_ / 32, NHN_ / 32, 1), tb>>>(dec,  p_decT_h, p_decT_l, NHN_, D_);
    k_tsplit<<<dim3(VOCAB_ / 32, D_ / 32, 1), tb>>>(lmh, p_lmhT_h, p_lmhT_l, D_, VOCAB_);
    k_embed_ln<<<T_, 256>>>(idx, embed);

    for (int l = 0; l < NL_; ++l) {
        k_enc<1><<<dim3(16, 16, NH_), 256>>>();
        k_scores<<<dim3(16, 16, NH_), 256>>>();
        k_ykv<<<dim3(2, 16, NH_), 256>>>();
        k_ln_ykv<<<NH_ * T_, 256>>>();
        k_enc<4><<<dim3(16, 16, NH_), 256>>>();
        k_dec<<<dim3(2, 16, 8), 256>>>();
        k_ln2<<<T_, 256>>>();
    }
    k_logits<<<dim3(2, 16, 1), 256>>>(out);
}